// round 1
// baseline (speedup 1.0000x reference)
#include <cuda_runtime.h>

// ---------------------------------------------------------------------------
// RealNVP forward: 6 coupling layers with batchnorm, two 32->512->512->32 MLPs
// per layer, then log-likelihood / loss.
//
// Output layout (float32), matching reference tuple order, flattened:
//   [0, N*D)            y
//   [N*D]               loss
//   [N*D+1, N*D+1+N)    log_likelihood
//   [N*D+1+N, N*D+1+2N) det_s
//   [N*D+1+2N]          log_likelihood.mean()
//   [N*D+2+2N]          det_s.mean()
// ---------------------------------------------------------------------------

#define NR 65536
#define DDIM 64
#define HID 512
#define EPSF 1e-5f
#define ND (NR * DDIM)

// 0.5 * D * log(2*pi)
#define HALF_D_LOG2PI 58.812066125099054f

// ---- device scratch (static allocations only; no cudaMalloc anywhere) ----
__device__ float g_part[512 * 128];   // per-block partial [sum(64) | sumsq(64)]
__device__ float g_mean[64];
__device__ float g_rstd[64];
__device__ float g_red[512];          // [block][2] partial (ll, det) sums

// ---------------------------------------------------------------------------
// batchnorm stats: partial sums per 128-row slab
// ---------------------------------------------------------------------------
__global__ void __launch_bounds__(256) bn_partial_kernel(const float* __restrict__ x)
{
    int t = threadIdx.x;
    int b = blockIdx.x;            // 512 blocks, 128 rows each
    int c  = t & 63;
    int rs = t >> 6;               // 0..3
    int base = b * 128 + rs;
    float s = 0.f, q = 0.f;
#pragma unroll
    for (int j = 0; j < 32; j++) {
        float v = x[(base + j * 4) * DDIM + c];
        s += v;
        q += v * v;
    }
    __shared__ float sh[2][256];
    sh[0][t] = s;
    sh[1][t] = q;
    __syncthreads();
    if (t < 64) {
        float ss = sh[0][t] + sh[0][t + 64] + sh[0][t + 128] + sh[0][t + 192];
        float qq = sh[1][t] + sh[1][t + 64] + sh[1][t + 128] + sh[1][t + 192];
        g_part[b * 128 + t]      = ss;
        g_part[b * 128 + 64 + t] = qq;
    }
}

__global__ void __launch_bounds__(256) bn_final_kernel()
{
    int t = threadIdx.x;           // 256
    int c = t & 63;
    int part = t >> 6;             // 0..3
    int b0  = (part & 1) * 256;    // which half of the 512 blocks
    int off = (part >> 1) * 64;    // 0 = sum, 64 = sumsq
    float a = 0.f;
#pragma unroll 8
    for (int b = b0; b < b0 + 256; b++)
        a += g_part[b * 128 + off + c];
    __shared__ float sh[256];
    sh[t] = a;
    __syncthreads();
    if (t < 64) {
        float mean = (sh[t] + sh[t + 64]) * (1.f / NR);
        float ex2  = (sh[t + 128] + sh[t + 192]) * (1.f / NR);
        g_mean[t] = mean;
        g_rstd[t] = rsqrtf(ex2 - mean * mean + EPSF);
    }
}

// ---------------------------------------------------------------------------
// Fused coupling layer: normalize, split, s/t MLPs, affine transform, det_s.
// 1 block = 32 rows, 256 threads, ~154 KB dynamic smem.
// ---------------------------------------------------------------------------
#define WS 520          // h1s / w2t row stride (floats)
#define W3S 36          // w3t row stride (floats)
#define SMEM_FLOATS (1152 * 3 + 32 * WS + 512 * 36)
#define SMEM_BYTES (SMEM_FLOATS * 4)

__global__ void __launch_bounds__(256, 1) coupling_kernel(
    const float* __restrict__ xin, float* __restrict__ xout, float* __restrict__ det,
    const float* __restrict__ sW1, const float* __restrict__ sb1,
    const float* __restrict__ sW2, const float* __restrict__ sb2,
    const float* __restrict__ sW3, const float* __restrict__ sb3,
    const float* __restrict__ tW1, const float* __restrict__ tb1,
    const float* __restrict__ tW2, const float* __restrict__ tb2,
    const float* __restrict__ tW3, const float* __restrict__ tb3,
    int layer)
{
    extern __shared__ float sm[];
    float* x1s = sm;                       // [32][36]
    float* x2s = sm + 1152;                // [32][36]
    float* ssm = sm + 2304;                // [32][36]
    float* h1s = sm + 3456;                // [32][WS]
    float* wt  = sm + 3456 + 32 * WS;      // [512*36] (k-major weight staging)

    const int t  = threadIdx.x;
    const int r0 = blockIdx.x * 32;
    const bool even = ((layer & 1) == 0);

    // ---- load tile, normalize, split into x1/x2 ----
#pragma unroll
    for (int j = 0; j < 8; j++) {
        int e = t + j * 256;
        int r = e >> 6, c = e & 63;
        float v = (xin[(r0 + r) * DDIM + c] - g_mean[c]) * g_rstd[c];
        int half = c >> 5, cc = c & 31;
        bool to1 = even ? (half == 0) : (half == 1);
        if (to1) x1s[r * 36 + cc] = v;
        else     x2s[r * 36 + cc] = v;
    }
    __syncthreads();

    const int tr  = t >> 6;   // 0..3  (8-row group)
    const int tc8 = (t & 63) * 8;  // col base for GEMM1/2
    const int r3  = t >> 3;   // 0..31 (GEMM3 row)
    const int og  = t & 7;    // 0..7  (GEMM3 4-col group)

    for (int flow = 0; flow < 2; flow++) {
        const float* W1 = flow ? tW1 : sW1;
        const float* b1 = flow ? tb1 : sb1;
        const float* W2 = flow ? tW2 : sW2;
        const float* b2 = flow ? tb2 : sb2;
        const float* W3 = flow ? tW3 : sW3;
        const float* b3 = flow ? tb3 : sb3;

        // ---- stage W1^T (k-major): wt[k*WS + h] = W1[h*32 + k] ----
#pragma unroll
        for (int j = 0; j < 64; j++) {
            int e = t + j * 256;
            int h = e >> 5, k = e & 31;
            wt[k * WS + h] = W1[e];
        }
        __syncthreads();

        // ---- GEMM1: h1[32][512] = relu(x1 @ W1^T + b1) ----
        float acc[8][8];
#pragma unroll
        for (int i = 0; i < 8; i++)
#pragma unroll
            for (int j = 0; j < 8; j++) acc[i][j] = 0.f;

#pragma unroll
        for (int kk = 0; kk < 32; kk += 4) {
            float4 a[8];
#pragma unroll
            for (int i = 0; i < 8; i++)
                a[i] = *(const float4*)&x1s[(tr * 8 + i) * 36 + kk];
#pragma unroll
            for (int k4 = 0; k4 < 4; k4++) {
                float4 w0 = *(const float4*)&wt[(kk + k4) * WS + tc8];
                float4 w1 = *(const float4*)&wt[(kk + k4) * WS + tc8 + 4];
#pragma unroll
                for (int i = 0; i < 8; i++) {
                    float av = ((const float*)&a[i])[k4];
                    acc[i][0] = fmaf(av, w0.x, acc[i][0]);
                    acc[i][1] = fmaf(av, w0.y, acc[i][1]);
                    acc[i][2] = fmaf(av, w0.z, acc[i][2]);
                    acc[i][3] = fmaf(av, w0.w, acc[i][3]);
                    acc[i][4] = fmaf(av, w1.x, acc[i][4]);
                    acc[i][5] = fmaf(av, w1.y, acc[i][5]);
                    acc[i][6] = fmaf(av, w1.z, acc[i][6]);
                    acc[i][7] = fmaf(av, w1.w, acc[i][7]);
                }
            }
        }
        {
            float bb[8];
#pragma unroll
            for (int j = 0; j < 8; j++) bb[j] = __ldg(&b1[tc8 + j]);
#pragma unroll
            for (int i = 0; i < 8; i++)
#pragma unroll
                for (int j = 0; j < 8; j++)
                    h1s[(tr * 8 + i) * WS + tc8 + j] = fmaxf(acc[i][j] + bb[j], 0.f);
        }

        // ---- GEMM2: h2[32][512] = relu(h1 @ W2^T + b2), K streamed 32-wide ----
        float acc2[8][8];
#pragma unroll
        for (int i = 0; i < 8; i++)
#pragma unroll
            for (int j = 0; j < 8; j++) acc2[i][j] = 0.f;

        for (int c0 = 0; c0 < HID; c0 += 32) {
            __syncthreads();   // wt reads (and first iter: h1s writes) done
#pragma unroll
            for (int j = 0; j < 64; j++) {
                int e = t + j * 256;
                int h = e >> 5, k = e & 31;
                wt[k * WS + h] = W2[h * HID + c0 + k];
            }
            __syncthreads();
#pragma unroll
            for (int kk = 0; kk < 32; kk += 4) {
                float4 a[8];
#pragma unroll
                for (int i = 0; i < 8; i++)
                    a[i] = *(const float4*)&h1s[(tr * 8 + i) * WS + c0 + kk];
#pragma unroll
                for (int k4 = 0; k4 < 4; k4++) {
                    float4 w0 = *(const float4*)&wt[(kk + k4) * WS + tc8];
                    float4 w1 = *(const float4*)&wt[(kk + k4) * WS + tc8 + 4];
#pragma unroll
                    for (int i = 0; i < 8; i++) {
                        float av = ((const float*)&a[i])[k4];
                        acc2[i][0] = fmaf(av, w0.x, acc2[i][0]);
                        acc2[i][1] = fmaf(av, w0.y, acc2[i][1]);
                        acc2[i][2] = fmaf(av, w0.z, acc2[i][2]);
                        acc2[i][3] = fmaf(av, w0.w, acc2[i][3]);
                        acc2[i][4] = fmaf(av, w1.x, acc2[i][4]);
                        acc2[i][5] = fmaf(av, w1.y, acc2[i][5]);
                        acc2[i][6] = fmaf(av, w1.z, acc2[i][6]);
                        acc2[i][7] = fmaf(av, w1.w, acc2[i][7]);
                    }
                }
            }
        }
        __syncthreads();   // everyone done reading h1s
        {
            float bb[8];
#pragma unroll
            for (int j = 0; j < 8; j++) bb[j] = __ldg(&b2[tc8 + j]);
#pragma unroll
            for (int i = 0; i < 8; i++)
#pragma unroll
                for (int j = 0; j < 8; j++)
                    h1s[(tr * 8 + i) * WS + tc8 + j] = fmaxf(acc2[i][j] + bb[j], 0.f);
        }
        __syncthreads();

        // ---- stage W3^T: wt[k*W3S + o] = W3[o*512 + k] ----
#pragma unroll
        for (int j = 0; j < 64; j++) {
            int e = t + j * 256;
            int o = e >> 9, k = e & 511;
            wt[k * W3S + o] = W3[o * HID + k];
        }
        __syncthreads();

        // ---- GEMM3: out[32][32] = h2 @ W3^T + b3 ----
        float a3[4] = {0.f, 0.f, 0.f, 0.f};
#pragma unroll 8
        for (int k = 0; k < HID; k++) {
            float av = h1s[r3 * WS + k];
            float4 w = *(const float4*)&wt[k * W3S + og * 4];
            a3[0] = fmaf(av, w.x, a3[0]);
            a3[1] = fmaf(av, w.y, a3[1]);
            a3[2] = fmaf(av, w.z, a3[2]);
            a3[3] = fmaf(av, w.w, a3[3]);
        }
        float bo[4];
#pragma unroll
        for (int j = 0; j < 4; j++) bo[j] = __ldg(&b3[og * 4 + j]);

        if (flow == 0) {
            float sv[4];
            float ps = 0.f;
#pragma unroll
            for (int j = 0; j < 4; j++) {
                sv[j] = a3[j] + bo[j];
                ssm[r3 * 36 + og * 4 + j] = sv[j];
                ps += sv[j];
            }
            // reduce across the 8 og lanes of this row
            ps += __shfl_down_sync(0xffffffffu, ps, 4, 8);
            ps += __shfl_down_sync(0xffffffffu, ps, 2, 8);
            ps += __shfl_down_sync(0xffffffffu, ps, 1, 8);
            if (og == 0) {
                float base = (layer == 0) ? 0.f : det[r0 + r3];
                det[r0 + r3] = base + ps;
            }
            __syncthreads();   // uniform: all threads are in flow 0 together
        } else {
#pragma unroll
            for (int j = 0; j < 4; j++) {
                float svv = ssm[r3 * 36 + og * 4 + j];
                float tv  = a3[j] + bo[j];
                float y2  = x2s[r3 * 36 + og * 4 + j] * expf(svv) + tv;
                xout[(r0 + r3) * DDIM + 32 + og * 4 + j] = y2;
            }
        }
    }

    __syncthreads();
    // x1 goes to output cols [0,32)
#pragma unroll
    for (int j = 0; j < 4; j++) {
        int e = t + j * 256;
        int r = e >> 5, c = e & 31;
        xout[(r0 + r) * DDIM + c] = x1s[r * 36 + c];
    }
}

// ---------------------------------------------------------------------------
// log-likelihood + partial reductions
// ---------------------------------------------------------------------------
__global__ void __launch_bounds__(256) loglik_kernel(const float* __restrict__ y,
                                                     float* __restrict__ out)
{
    int t = threadIdx.x;
    int r = blockIdx.x * 256 + t;
    const float4* row = (const float4*)(y + r * DDIM);
    float s = 0.f;
#pragma unroll
    for (int j = 0; j < 16; j++) {
        float4 v = row[j];
        s += v.x * v.x + v.y * v.y + v.z * v.z + v.w * v.w;
    }
    float ll = -0.5f * s - HALF_D_LOG2PI;
    out[ND + 1 + r] = ll;
    float dv = out[ND + 1 + NR + r];

    __shared__ float sh[512];
    sh[t] = ll;
    sh[256 + t] = dv;
    __syncthreads();
    for (int o = 128; o >= 1; o >>= 1) {
        if (t < o) { sh[t] += sh[t + o]; sh[256 + t] += sh[256 + t + o]; }
        __syncthreads();
    }
    if (t == 0) {
        g_red[blockIdx.x * 2]     = sh[0];
        g_red[blockIdx.x * 2 + 1] = sh[256];
    }
}

__global__ void __launch_bounds__(256) final_kernel(float* __restrict__ out)
{
    int t = threadIdx.x;   // 256
    __shared__ float sh[512];
    sh[t]       = g_red[t * 2];
    sh[256 + t] = g_red[t * 2 + 1];
    __syncthreads();
    for (int o = 128; o >= 1; o >>= 1) {
        if (t < o) { sh[t] += sh[t + o]; sh[256 + t] += sh[256 + t + o]; }
        __syncthreads();
    }
    if (t == 0) {
        float ll_mean  = sh[0]   * (1.f / NR);
        float det_mean = sh[256] * (1.f / NR);
        out[ND]              = -(det_mean + ll_mean);
        out[ND + 1 + 2 * NR]     = ll_mean;
        out[ND + 2 + 2 * NR]     = det_mean;
    }
}

// ---------------------------------------------------------------------------
// launch
// ---------------------------------------------------------------------------
extern "C" void kernel_launch(void* const* d_in, const int* in_sizes, int n_in,
                              void* d_out, int out_size)
{
    (void)in_sizes; (void)n_in; (void)out_size;
    const float* x   = (const float*)d_in[0];
    const float* sW1 = (const float*)d_in[1];
    const float* sb1 = (const float*)d_in[2];
    const float* sW2 = (const float*)d_in[3];
    const float* sb2 = (const float*)d_in[4];
    const float* sW3 = (const float*)d_in[5];
    const float* sb3 = (const float*)d_in[6];
    const float* tW1 = (const float*)d_in[7];
    const float* tb1 = (const float*)d_in[8];
    const float* tW2 = (const float*)d_in[9];
    const float* tb2 = (const float*)d_in[10];
    const float* tW3 = (const float*)d_in[11];
    const float* tb3 = (const float*)d_in[12];

    float* out = (float*)d_out;
    float* y   = out;                       // x buffer lives in the y region
    float* det = out + ND + 1 + NR;         // det_s region

    cudaFuncSetAttribute(coupling_kernel,
                         cudaFuncAttributeMaxDynamicSharedMemorySize, SMEM_BYTES);

    for (int L = 0; L < 6; L++) {
        const float* xc = (L == 0) ? x : y;
        bn_partial_kernel<<<512, 256>>>(xc);
        bn_final_kernel<<<1, 256>>>();
        coupling_kernel<<<2048, 256, SMEM_BYTES>>>(
            xc, y, det,
            sW1 + L * HID * 32, sb1 + L * HID,
            sW2 + L * HID * HID, sb2 + L * HID,
            sW3 + L * 32 * HID, sb3 + L * 32,
            tW1 + L * HID * 32, tb1 + L * HID,
            tW2 + L * HID * HID, tb2 + L * HID,
            tW3 + L * 32 * HID, tb3 + L * 32,
            L);
    }
    loglik_kernel<<<256, 256>>>(y, out);
    final_kernel<<<1, 256>>>(out);
}

// round 3
// speedup vs baseline: 1.0001x; 1.0001x over previous
#include <cuda_runtime.h>

// ---------------------------------------------------------------------------
// RealNVP forward: 6 coupling layers with batchnorm, two 32->512->512->32 MLPs
// per layer, then log-likelihood / loss.
//
// Output layout (float32), matching reference tuple order, flattened:
//   [0, N*D)            y
//   [N*D]               loss
//   [N*D+1, N*D+1+N)    log_likelihood
//   [N*D+1+N, N*D+1+2N) det_s
//   [N*D+1+2N]          log_likelihood.mean()
//   [N*D+2+2N]          det_s.mean()
// ---------------------------------------------------------------------------

#define NR 65536
#define DDIM 64
#define HID 512
#define EPSF 1e-5f
#define ND (NR * DDIM)

// 0.5 * D * log(2*pi)
#define HALF_D_LOG2PI 58.812066125099054f

// ---- device scratch (static allocations only; no cudaMalloc anywhere) ----
__device__ float g_part[512 * 128];   // per-block partial [sum(64) | sumsq(64)]
__device__ float g_mean[64];
__device__ float g_rstd[64];
__device__ float g_red[512];          // [block][2] partial (ll, det) sums

// ---------------------------------------------------------------------------
// batchnorm stats: partial sums per 128-row slab
// ---------------------------------------------------------------------------
__global__ void __launch_bounds__(256) bn_partial_kernel(const float* __restrict__ x)
{
    int t = threadIdx.x;
    int b = blockIdx.x;            // 512 blocks, 128 rows each
    int c  = t & 63;
    int rs = t >> 6;               // 0..3
    int base = b * 128 + rs;
    float s = 0.f, q = 0.f;
#pragma unroll
    for (int j = 0; j < 32; j++) {
        float v = x[(base + j * 4) * DDIM + c];
        s += v;
        q += v * v;
    }
    __shared__ float sh[2][256];
    sh[0][t] = s;
    sh[1][t] = q;
    __syncthreads();
    if (t < 64) {
        float ss = sh[0][t] + sh[0][t + 64] + sh[0][t + 128] + sh[0][t + 192];
        float qq = sh[1][t] + sh[1][t + 64] + sh[1][t + 128] + sh[1][t + 192];
        g_part[b * 128 + t]      = ss;
        g_part[b * 128 + 64 + t] = qq;
    }
}

__global__ void __launch_bounds__(256) bn_final_kernel()
{
    int t = threadIdx.x;           // 256
    int c = t & 63;
    int part = t >> 6;             // 0..3
    int b0  = (part & 1) * 256;    // which half of the 512 blocks
    int off = (part >> 1) * 64;    // 0 = sum, 64 = sumsq
    float a = 0.f;
#pragma unroll 8
    for (int b = b0; b < b0 + 256; b++)
        a += g_part[b * 128 + off + c];
    __shared__ float sh[256];
    sh[t] = a;
    __syncthreads();
    if (t < 64) {
        float mean = (sh[t] + sh[t + 64]) * (1.f / NR);
        float ex2  = (sh[t + 128] + sh[t + 192]) * (1.f / NR);
        g_mean[t] = mean;
        g_rstd[t] = rsqrtf(ex2 - mean * mean + EPSF);
    }
}

// ---------------------------------------------------------------------------
// Fused coupling layer: normalize, split, s/t MLPs, affine transform, det_s.
// 1 block = 32 rows, 256 threads, ~154 KB dynamic smem.
// ---------------------------------------------------------------------------
#define WS 520          // h1s / w2t row stride (floats)
#define W3S 36          // w3t row stride (floats)
#define SMEM_FLOATS (1152 * 3 + 32 * WS + 512 * 36)
#define SMEM_BYTES (SMEM_FLOATS * 4)

__global__ void __launch_bounds__(256, 1) coupling_kernel(
    const float* __restrict__ xin, float* __restrict__ xout, float* __restrict__ det,
    const float* __restrict__ sW1, const float* __restrict__ sb1,
    const float* __restrict__ sW2, const float* __restrict__ sb2,
    const float* __restrict__ sW3, const float* __restrict__ sb3,
    const float* __restrict__ tW1, const float* __restrict__ tb1,
    const float* __restrict__ tW2, const float* __restrict__ tb2,
    const float* __restrict__ tW3, const float* __restrict__ tb3,
    int layer)
{
    extern __shared__ float sm[];
    float* x1s = sm;                       // [32][36]
    float* x2s = sm + 1152;                // [32][36]
    float* ssm = sm + 2304;                // [32][36]
    float* h1s = sm + 3456;                // [32][WS]
    float* wt  = sm + 3456 + 32 * WS;      // [512*36] (k-major weight staging)

    const int t  = threadIdx.x;
    const int r0 = blockIdx.x * 32;
    const bool even = ((layer & 1) == 0);

    // ---- load tile, normalize, split into x1/x2 ----
#pragma unroll
    for (int j = 0; j < 8; j++) {
        int e = t + j * 256;
        int r = e >> 6, c = e & 63;
        float v = (xin[(r0 + r) * DDIM + c] - g_mean[c]) * g_rstd[c];
        int half = c >> 5, cc = c & 31;
        bool to1 = even ? (half == 0) : (half == 1);
        if (to1) x1s[r * 36 + cc] = v;
        else     x2s[r * 36 + cc] = v;
    }
    __syncthreads();

    const int tr  = t >> 6;   // 0..3  (8-row group)
    const int tc8 = (t & 63) * 8;  // col base for GEMM1/2
    const int r3  = t >> 3;   // 0..31 (GEMM3 row)
    const int og  = t & 7;    // 0..7  (GEMM3 4-col group)

    for (int flow = 0; flow < 2; flow++) {
        const float* W1 = flow ? tW1 : sW1;
        const float* b1 = flow ? tb1 : sb1;
        const float* W2 = flow ? tW2 : sW2;
        const float* b2 = flow ? tb2 : sb2;
        const float* W3 = flow ? tW3 : sW3;
        const float* b3 = flow ? tb3 : sb3;

        // ---- stage W1^T (k-major): wt[k*WS + h] = W1[h*32 + k] ----
#pragma unroll
        for (int j = 0; j < 64; j++) {
            int e = t + j * 256;
            int h = e >> 5, k = e & 31;
            wt[k * WS + h] = W1[e];
        }
        __syncthreads();

        // ---- GEMM1: h1[32][512] = relu(x1 @ W1^T + b1) ----
        float acc[8][8];
#pragma unroll
        for (int i = 0; i < 8; i++)
#pragma unroll
            for (int j = 0; j < 8; j++) acc[i][j] = 0.f;

#pragma unroll
        for (int kk = 0; kk < 32; kk += 4) {
            float4 a[8];
#pragma unroll
            for (int i = 0; i < 8; i++)
                a[i] = *(const float4*)&x1s[(tr * 8 + i) * 36 + kk];
#pragma unroll
            for (int k4 = 0; k4 < 4; k4++) {
                float4 w0 = *(const float4*)&wt[(kk + k4) * WS + tc8];
                float4 w1 = *(const float4*)&wt[(kk + k4) * WS + tc8 + 4];
#pragma unroll
                for (int i = 0; i < 8; i++) {
                    float av = ((const float*)&a[i])[k4];
                    acc[i][0] = fmaf(av, w0.x, acc[i][0]);
                    acc[i][1] = fmaf(av, w0.y, acc[i][1]);
                    acc[i][2] = fmaf(av, w0.z, acc[i][2]);
                    acc[i][3] = fmaf(av, w0.w, acc[i][3]);
                    acc[i][4] = fmaf(av, w1.x, acc[i][4]);
                    acc[i][5] = fmaf(av, w1.y, acc[i][5]);
                    acc[i][6] = fmaf(av, w1.z, acc[i][6]);
                    acc[i][7] = fmaf(av, w1.w, acc[i][7]);
                }
            }
        }
        {
            float bb[8];
#pragma unroll
            for (int j = 0; j < 8; j++) bb[j] = __ldg(&b1[tc8 + j]);
#pragma unroll
            for (int i = 0; i < 8; i++)
#pragma unroll
                for (int j = 0; j < 8; j++)
                    h1s[(tr * 8 + i) * WS + tc8 + j] = fmaxf(acc[i][j] + bb[j], 0.f);
        }

        // ---- GEMM2: h2[32][512] = relu(h1 @ W2^T + b2), K streamed 32-wide ----
        float acc2[8][8];
#pragma unroll
        for (int i = 0; i < 8; i++)
#pragma unroll
            for (int j = 0; j < 8; j++) acc2[i][j] = 0.f;

        for (int c0 = 0; c0 < HID; c0 += 32) {
            __syncthreads();   // wt reads (and first iter: h1s writes) done
#pragma unroll
            for (int j = 0; j < 64; j++) {
                int e = t + j * 256;
                int h = e >> 5, k = e & 31;
                wt[k * WS + h] = W2[h * HID + c0 + k];
            }
            __syncthreads();
#pragma unroll
            for (int kk = 0; kk < 32; kk += 4) {
                float4 a[8];
#pragma unroll
                for (int i = 0; i < 8; i++)
                    a[i] = *(const float4*)&h1s[(tr * 8 + i) * WS + c0 + kk];
#pragma unroll
                for (int k4 = 0; k4 < 4; k4++) {
                    float4 w0 = *(const float4*)&wt[(kk + k4) * WS + tc8];
                    float4 w1 = *(const float4*)&wt[(kk + k4) * WS + tc8 + 4];
#pragma unroll
                    for (int i = 0; i < 8; i++) {
                        float av = ((const float*)&a[i])[k4];
                        acc2[i][0] = fmaf(av, w0.x, acc2[i][0]);
                        acc2[i][1] = fmaf(av, w0.y, acc2[i][1]);
                        acc2[i][2] = fmaf(av, w0.z, acc2[i][2]);
                        acc2[i][3] = fmaf(av, w0.w, acc2[i][3]);
                        acc2[i][4] = fmaf(av, w1.x, acc2[i][4]);
                        acc2[i][5] = fmaf(av, w1.y, acc2[i][5]);
                        acc2[i][6] = fmaf(av, w1.z, acc2[i][6]);
                        acc2[i][7] = fmaf(av, w1.w, acc2[i][7]);
                    }
                }
            }
        }
        __syncthreads();   // everyone done reading h1s
        {
            float bb[8];
#pragma unroll
            for (int j = 0; j < 8; j++) bb[j] = __ldg(&b2[tc8 + j]);
#pragma unroll
            for (int i = 0; i < 8; i++)
#pragma unroll
                for (int j = 0; j < 8; j++)
                    h1s[(tr * 8 + i) * WS + tc8 + j] = fmaxf(acc2[i][j] + bb[j], 0.f);
        }
        __syncthreads();

        // ---- stage W3^T: wt[k*W3S + o] = W3[o*512 + k] ----
#pragma unroll
        for (int j = 0; j < 64; j++) {
            int e = t + j * 256;
            int o = e >> 9, k = e & 511;
            wt[k * W3S + o] = W3[o * HID + k];
        }
        __syncthreads();

        // ---- GEMM3: out[32][32] = h2 @ W3^T + b3 ----
        float a3[4] = {0.f, 0.f, 0.f, 0.f};
#pragma unroll 8
        for (int k = 0; k < HID; k++) {
            float av = h1s[r3 * WS + k];
            float4 w = *(const float4*)&wt[k * W3S + og * 4];
            a3[0] = fmaf(av, w.x, a3[0]);
            a3[1] = fmaf(av, w.y, a3[1]);
            a3[2] = fmaf(av, w.z, a3[2]);
            a3[3] = fmaf(av, w.w, a3[3]);
        }
        float bo[4];
#pragma unroll
        for (int j = 0; j < 4; j++) bo[j] = __ldg(&b3[og * 4 + j]);

        if (flow == 0) {
            float sv[4];
            float ps = 0.f;
#pragma unroll
            for (int j = 0; j < 4; j++) {
                sv[j] = a3[j] + bo[j];
                ssm[r3 * 36 + og * 4 + j] = sv[j];
                ps += sv[j];
            }
            // reduce across the 8 og lanes of this row
            ps += __shfl_down_sync(0xffffffffu, ps, 4, 8);
            ps += __shfl_down_sync(0xffffffffu, ps, 2, 8);
            ps += __shfl_down_sync(0xffffffffu, ps, 1, 8);
            if (og == 0) {
                float base = (layer == 0) ? 0.f : det[r0 + r3];
                det[r0 + r3] = base + ps;
            }
            __syncthreads();   // uniform: all threads are in flow 0 together
        } else {
#pragma unroll
            for (int j = 0; j < 4; j++) {
                float svv = ssm[r3 * 36 + og * 4 + j];
                float tv  = a3[j] + bo[j];
                float y2  = x2s[r3 * 36 + og * 4 + j] * expf(svv) + tv;
                xout[(r0 + r3) * DDIM + 32 + og * 4 + j] = y2;
            }
        }
    }

    __syncthreads();
    // x1 goes to output cols [0,32)
#pragma unroll
    for (int j = 0; j < 4; j++) {
        int e = t + j * 256;
        int r = e >> 5, c = e & 31;
        xout[(r0 + r) * DDIM + c] = x1s[r * 36 + c];
    }
}

// ---------------------------------------------------------------------------
// log-likelihood + partial reductions
// ---------------------------------------------------------------------------
__global__ void __launch_bounds__(256) loglik_kernel(const float* __restrict__ y,
                                                     float* __restrict__ out)
{
    int t = threadIdx.x;
    int r = blockIdx.x * 256 + t;
    const float4* row = (const float4*)(y + r * DDIM);
    float s = 0.f;
#pragma unroll
    for (int j = 0; j < 16; j++) {
        float4 v = row[j];
        s += v.x * v.x + v.y * v.y + v.z * v.z + v.w * v.w;
    }
    float ll = -0.5f * s - HALF_D_LOG2PI;
    out[ND + 1 + r] = ll;
    float dv = out[ND + 1 + NR + r];

    __shared__ float sh[512];
    sh[t] = ll;
    sh[256 + t] = dv;
    __syncthreads();
    for (int o = 128; o >= 1; o >>= 1) {
        if (t < o) { sh[t] += sh[t + o]; sh[256 + t] += sh[256 + t + o]; }
        __syncthreads();
    }
    if (t == 0) {
        g_red[blockIdx.x * 2]     = sh[0];
        g_red[blockIdx.x * 2 + 1] = sh[256];
    }
}

__global__ void __launch_bounds__(256) final_kernel(float* __restrict__ out)
{
    int t = threadIdx.x;   // 256
    __shared__ float sh[512];
    sh[t]       = g_red[t * 2];
    sh[256 + t] = g_red[t * 2 + 1];
    __syncthreads();
    for (int o = 128; o >= 1; o >>= 1) {
        if (t < o) { sh[t] += sh[t + o]; sh[256 + t] += sh[256 + t + o]; }
        __syncthreads();
    }
    if (t == 0) {
        float ll_mean  = sh[0]   * (1.f / NR);
        float det_mean = sh[256] * (1.f / NR);
        out[ND]              = -(det_mean + ll_mean);
        out[ND + 1 + 2 * NR]     = ll_mean;
        out[ND + 2 + 2 * NR]     = det_mean;
    }
}

// ---------------------------------------------------------------------------
// launch
// ---------------------------------------------------------------------------
extern "C" void kernel_launch(void* const* d_in, const int* in_sizes, int n_in,
                              void* d_out, int out_size)
{
    (void)in_sizes; (void)n_in; (void)out_size;
    const float* x   = (const float*)d_in[0];
    const float* sW1 = (const float*)d_in[1];
    const float* sb1 = (const float*)d_in[2];
    const float* sW2 = (const float*)d_in[3];
    const float* sb2 = (const float*)d_in[4];
    const float* sW3 = (const float*)d_in[5];
    const float* sb3 = (const float*)d_in[6];
    const float* tW1 = (const float*)d_in[7];
    const float* tb1 = (const float*)d_in[8];
    const float* tW2 = (const float*)d_in[9];
    const float* tb2 = (const float*)d_in[10];
    const float* tW3 = (const float*)d_in[11];
    const float* tb3 = (const float*)d_in[12];

    float* out = (float*)d_out;
    float* y   = out;                       // x buffer lives in the y region
    float* det = out + ND + 1 + NR;         // det_s region

    cudaFuncSetAttribute(coupling_kernel,
                         cudaFuncAttributeMaxDynamicSharedMemorySize, SMEM_BYTES);

    for (int L = 0; L < 6; L++) {
        const float* xc = (L == 0) ? x : y;
        bn_partial_kernel<<<512, 256>>>(xc);
        bn_final_kernel<<<1, 256>>>();
        coupling_kernel<<<2048, 256, SMEM_BYTES>>>(
            xc, y, det,
            sW1 + L * HID * 32, sb1 + L * HID,
            sW2 + L * HID * HID, sb2 + L * HID,
            sW3 + L * 32 * HID, sb3 + L * 32,
            tW1 + L * HID * 32, tb1 + L * HID,
            tW2 + L * HID * HID, tb2 + L * HID,
            tW3 + L * 32 * HID, tb3 + L * 32,
            L);
    }
    loglik_kernel<<<256, 256>>>(y, out);
    final_kernel<<<1, 256>>>(out);
}